// round 1
// baseline (speedup 1.0000x reference)
#include <cuda_runtime.h>
#include <math.h>

// Problem constants
#define Tn 16384            // B*N tokens
#define Dd 768
#define Ff 3072
#define Ee 16
#define CAPc 160
#define Bbat 8
#define Nseq 2048

// Output layout (float32, concatenated in reference return order)
#define OFF_AUX    12582912
#define OFF_BAL    12582913
#define OFF_ZL     12582914
#define OFF_LOGITS 12582915ll
#define OFF_ENERGY 12845059ll
#define OFF_GIDX   12861443ll

// ---------------- scratch (device globals; no runtime allocation) ----------------
__device__ float g_wi[(size_t)Tn * Dd];     // RMS-normed input
__device__ float g_h [(size_t)Tn * Ff];     // z, then h in-place
__device__ float g_w [(size_t)Tn * Dd];     // h @ Wo^T
__device__ float g_u1[2 * Tn * 16];         // LoRA u for wi path, per (rank, token)
__device__ float g_u2[2 * Tn * 16];         // LoRA u for wo path
__device__ int   g_e  [2 * Tn];             // expert id per (rank, token)
__device__ float g_gate[2 * Tn];            // normalized gates
__device__ float g_gp  [2 * Tn];            // gate after drop (0 if dropped)
__device__ int   g_sh1 [Tn];                // stochastic 2nd-expert flag
__device__ float g_dp[Bbat * Ee];           // density_proxy sums
__device__ float g_d1[Bbat * Ee];           // density_1
__device__ float g_zl;                      // sum lse^2

// ---------------- init (must re-zero accumulators every replay) ----------------
__global__ void k_init() {
    int i = threadIdx.x;
    if (i < Bbat * Ee) g_dp[i] = 0.f;
    if (i == 0) g_zl = 0.f;
}

// ---------------- RMS norm ----------------
__global__ __launch_bounds__(256) void k_rms(const float* __restrict__ x,
                                             const float* __restrict__ lnw) {
    int t = blockIdx.x;
    const float* xr = x + (size_t)t * Dd;
    float s = 0.f;
    for (int d = threadIdx.x; d < Dd; d += 256) { float v = xr[d]; s += v * v; }
    __shared__ float red[256];
    red[threadIdx.x] = s; __syncthreads();
    for (int o = 128; o > 0; o >>= 1) {
        if (threadIdx.x < o) red[threadIdx.x] += red[threadIdx.x + o];
        __syncthreads();
    }
    float inv = rsqrtf(red[0] / (float)Dd + 1e-6f);
    for (int d = threadIdx.x; d < Dd; d += 256)
        g_wi[(size_t)t * Dd + d] = xr[d] * inv * lnw[d];
}

// ---------------- logits = wi_in @ Wg^T ----------------
__global__ __launch_bounds__(256) void k_logits(const float* __restrict__ Wg,
                                                float* __restrict__ out) {
    __shared__ float sWg[Dd * 16];  // layout [d][e] -> conflict-free
    for (int i = threadIdx.x; i < Dd * 16; i += 256) {
        int e = i / Dd, d = i % Dd;
        sWg[d * 16 + e] = Wg[i];
    }
    __syncthreads();
    int tok = blockIdx.x * 16 + (threadIdx.x >> 4);
    int e = threadIdx.x & 15;
    const float* wr = g_wi + (size_t)tok * Dd;
    float s = 0.f;
    #pragma unroll 4
    for (int d = 0; d < Dd; d++) s += wr[d] * sWg[d * 16 + e];
    out[OFF_LOGITS + (size_t)tok * 16 + e] = s;
}

// ---------------- softmax / top2 / gates / aux partials ----------------
__global__ __launch_bounds__(256) void k_gate(const float* __restrict__ rp,
                                              float* __restrict__ out) {
    int t = blockIdx.x * 256 + threadIdx.x;
    const float* lg = out + OFF_LOGITS + (size_t)t * 16;
    float l[16];
    float mx = -1e30f;
    #pragma unroll
    for (int e = 0; e < 16; e++) { l[e] = lg[e]; mx = fmaxf(mx, l[e]); }
    float se = 0.f;
    #pragma unroll
    for (int e = 0; e < 16; e++) se += expf(l[e] - mx);
    float lse = mx + logf(se);
    out[OFF_ENERGY + t] = -lse;

    int e0 = 0; float b0 = l[0];
    #pragma unroll
    for (int e = 1; e < 16; e++) if (l[e] > b0) { b0 = l[e]; e0 = e; }
    int e1 = -1; float b1 = -1e30f;
    #pragma unroll
    for (int e = 0; e < 16; e++) if (e != e0 && l[e] > b1) { b1 = l[e]; e1 = e; }
    float v0 = expf(b0 - lse), v1 = expf(b1 - lse);
    float den = v0 + v1; if (den < 1e-9f) den = 1e-9f;
    float G0 = v0 / den, G1 = v1 / den;
    g_e[t] = e0; g_e[Tn + t] = e1;
    g_gate[t] = G0; g_gate[Tn + t] = G1;
    g_sh1[t] = (rp[Tn + t] < G1 * 5.0f) ? 1 : 0;   // route_probs[1,b,n] < g1/0.2

    // block-local reductions (each block fully inside one batch b)
    __shared__ float sdp[16];
    __shared__ float szl;
    if (threadIdx.x < 16) sdp[threadIdx.x] = 0.f;
    if (threadIdx.x == 0) szl = 0.f;
    __syncthreads();
    #pragma unroll
    for (int e = 0; e < 16; e++) atomicAdd(&sdp[e], expf(l[e] - lse));
    atomicAdd(&szl, lse * lse);
    __syncthreads();
    int b = t >> 11;
    if (threadIdx.x < 16) atomicAdd(&g_dp[b * 16 + threadIdx.x], sdp[threadIdx.x]);
    if (threadIdx.x == 0) atomicAdd(&g_zl, szl);
}

// ---------------- capacity scan (sequential over n per batch) ----------------
__global__ void k_scan(float* __restrict__ out) {
    if (threadIdx.x != 0) return;
    int b = blockIdx.x;
    int base = b * Nseq;
    int c0[16];
    #pragma unroll
    for (int e = 0; e < 16; e++) c0[e] = 0;
    for (int n = 0; n < Nseq; n++) {
        int t = base + n;
        int e = g_e[t];
        int pos = c0[e]++;                 // cumsum counts even dropped tokens
        bool s = pos < CAPc;
        g_gp[t] = s ? g_gate[t] : 0.f;
        out[OFF_GIDX + t] = s ? (float)e : 0.f;
    }
    int c1[16];
    #pragma unroll
    for (int e = 0; e < 16; e++) {
        int sv = c0[e] < CAPc ? c0[e] : CAPc;
        g_d1[b * 16 + e] = (float)sv / (float)Nseq;
        c1[e] = sv;                        // k=1 positions start after surviving k=0
    }
    for (int n = 0; n < Nseq; n++) {
        int t = base + n;
        if (g_sh1[t]) {
            int e = g_e[Tn + t];
            int pos = c1[e]++;
            bool s = pos < CAPc;
            g_gp[Tn + t] = s ? g_gate[Tn + t] : 0.f;
            out[OFF_GIDX + Tn + t] = s ? (float)e : 0.f;
        } else {
            g_gp[Tn + t] = 0.f;
            out[OFF_GIDX + Tn + t] = 0.f;
        }
    }
}

// ---------------- aux scalars ----------------
__global__ void k_aux(float* __restrict__ out) {
    __shared__ float red[128];
    int i = threadIdx.x;
    red[i] = (g_dp[i] / (float)Nseq) * g_d1[i];
    __syncthreads();
    for (int o = 64; o > 0; o >>= 1) {
        if (i < o) red[i] += red[i + o];
        __syncthreads();
    }
    if (i == 0) {
        float bal = red[0] * 2.0f;          // mean * E*E = (sum/128)*256
        float zl = g_zl / (float)Tn;
        out[OFF_BAL] = bal;
        out[OFF_ZL] = zl;
        out[OFF_AUX] = 0.01f * bal + 0.01f * zl;
    }
}

// ---------------- LoRA u vectors: u = wi_in[t] @ Ai[e]  (R=16) ----------------
__global__ __launch_bounds__(128) void k_u1(const float* __restrict__ Ai) {
    int t = blockIdx.x, k = blockIdx.y;
    int idx = k * Tn + t;
    float gp = g_gp[idx];
    if (gp == 0.f) {
        if (threadIdx.x < 16) g_u1[idx * 16 + threadIdx.x] = 0.f;
        return;
    }
    int e = g_e[idx];
    int r = threadIdx.x & 15, seg = threadIdx.x >> 4;   // 8 segments of 96
    const float* Ae = Ai + (size_t)e * Dd * 16;
    const float* wr = g_wi + (size_t)t * Dd;
    float acc = 0.f;
    int d0 = seg * 96;
    #pragma unroll 4
    for (int d = d0; d < d0 + 96; d++) acc += wr[d] * Ae[d * 16 + r];
    __shared__ float red[128];
    red[threadIdx.x] = acc; __syncthreads();
    if (threadIdx.x < 16) {
        float s = 0.f;
        #pragma unroll
        for (int j = 0; j < 8; j++) s += red[j * 16 + r];
        g_u1[idx * 16 + r] = s;
    }
}

__global__ __launch_bounds__(128) void k_u2(const float* __restrict__ Ao) {
    int t = blockIdx.x, k = blockIdx.y;
    int idx = k * Tn + t;
    float gp = g_gp[idx];
    if (gp == 0.f) {
        if (threadIdx.x < 16) g_u2[idx * 16 + threadIdx.x] = 0.f;
        return;
    }
    int e = g_e[idx];
    int r = threadIdx.x & 15, seg = threadIdx.x >> 4;   // 8 segments of 384
    const float* Ae = Ao + (size_t)e * Ff * 16;
    const float* hr = g_h + (size_t)t * Ff;
    float acc = 0.f;
    int d0 = seg * 384;
    #pragma unroll 4
    for (int d = d0; d < d0 + 384; d++) acc += hr[d] * Ae[d * 16 + r];
    __shared__ float red[128];
    red[threadIdx.x] = acc; __syncthreads();
    if (threadIdx.x < 16) {
        float s = 0.f;
        #pragma unroll
        for (int j = 0; j < 8; j++) s += red[j * 16 + r];
        g_u2[idx * 16 + r] = s;
    }
}

// ---------------- generic tiled fp32 GEMM: C[m,n] = sum_k A[m,k]*B[n,k] ----------------
__device__ __forceinline__ void gemm_body(const float* __restrict__ A,
                                          const float* __restrict__ B,
                                          float* __restrict__ C,
                                          int Ncols, int Kd) {
    __shared__ float As[8][128];
    __shared__ float Bs[8][128];
    const int tid = threadIdx.x;
    const int bm = blockIdx.y * 128;
    const int bn = blockIdx.x * 128;
    const int lrow = tid >> 1;
    const int lcol = (tid & 1) << 2;
    const int ty = tid >> 4;
    const int tx = tid & 15;
    float acc[8][8];
    #pragma unroll
    for (int i = 0; i < 8; i++)
        #pragma unroll
        for (int j = 0; j < 8; j++) acc[i][j] = 0.f;

    const float* Ap = A + (size_t)(bm + lrow) * Kd + lcol;
    const float* Bp = B + (size_t)(bn + lrow) * Kd + lcol;

    for (int k0 = 0; k0 < Kd; k0 += 8) {
        float4 av = *(const float4*)(Ap + k0);
        float4 bv = *(const float4*)(Bp + k0);
        As[lcol + 0][lrow] = av.x; As[lcol + 1][lrow] = av.y;
        As[lcol + 2][lrow] = av.z; As[lcol + 3][lrow] = av.w;
        Bs[lcol + 0][lrow] = bv.x; Bs[lcol + 1][lrow] = bv.y;
        Bs[lcol + 2][lrow] = bv.z; Bs[lcol + 3][lrow] = bv.w;
        __syncthreads();
        #pragma unroll
        for (int kk = 0; kk < 8; kk++) {
            float4 ra0 = *(const float4*)&As[kk][ty * 8];
            float4 ra1 = *(const float4*)&As[kk][ty * 8 + 4];
            float4 rb0 = *(const float4*)&Bs[kk][tx * 8];
            float4 rb1 = *(const float4*)&Bs[kk][tx * 8 + 4];
            float ra[8] = {ra0.x, ra0.y, ra0.z, ra0.w, ra1.x, ra1.y, ra1.z, ra1.w};
            float rb[8] = {rb0.x, rb0.y, rb0.z, rb0.w, rb1.x, rb1.y, rb1.z, rb1.w};
            #pragma unroll
            for (int i = 0; i < 8; i++)
                #pragma unroll
                for (int j = 0; j < 8; j++) acc[i][j] += ra[i] * rb[j];
        }
        __syncthreads();
    }
    #pragma unroll
    for (int i = 0; i < 8; i++) {
        float* cp = C + (size_t)(bm + ty * 8 + i) * Ncols + bn + tx * 8;
        float4 v0 = make_float4(acc[i][0], acc[i][1], acc[i][2], acc[i][3]);
        float4 v1 = make_float4(acc[i][4], acc[i][5], acc[i][6], acc[i][7]);
        *(float4*)cp = v0;
        *(float4*)(cp + 4) = v1;
    }
}

__global__ __launch_bounds__(256) void k_gemm1(const float* __restrict__ Wi) {
    gemm_body(g_wi, Wi, g_h, Ff, Dd);       // z = wi_in @ Wi^T
}
__global__ __launch_bounds__(256) void k_gemm2(const float* __restrict__ Wo) {
    gemm_body(g_h, Wo, g_w, Dd, Ff);        // w = h @ Wo^T
}

// ---------------- h = relu(z) + sum_k g'_k (z + 2 * u_k @ Bi[e_k]) ----------------
__global__ __launch_bounds__(256) void k_h(const float* __restrict__ Bi) {
    int t = blockIdx.x;
    float g0 = g_gp[t], g1 = g_gp[Tn + t];
    int e0 = g_e[t], e1 = g_e[Tn + t];
    __shared__ float su0[16], su1[16];
    if (threadIdx.x < 16) {
        su0[threadIdx.x] = g_u1[t * 16 + threadIdx.x];
        su1[threadIdx.x] = g_u1[(Tn + t) * 16 + threadIdx.x];
    }
    __syncthreads();
    float gs = g0 + g1;
    const float* B0 = Bi + (size_t)e0 * 16 * Ff;
    const float* B1 = Bi + (size_t)e1 * 16 * Ff;
    float* hr = g_h + (size_t)t * Ff;
    for (int f = threadIdx.x; f < Ff; f += 256) {
        float z = hr[f];
        float acc = fmaxf(z, 0.f) + gs * z;
        if (g0 != 0.f) {
            float dsum = 0.f;
            #pragma unroll
            for (int r = 0; r < 16; r++) dsum += su0[r] * B0[r * Ff + f];
            acc += 2.f * g0 * dsum;
        }
        if (g1 != 0.f) {
            float dsum = 0.f;
            #pragma unroll
            for (int r = 0; r < 16; r++) dsum += su1[r] * B1[r * Ff + f];
            acc += 2.f * g1 * dsum;
        }
        hr[f] = acc;
    }
}

// ---------------- out = x + w + sum_k g'_k (w + 2 * u2_k @ Bo[e_k]) ----------------
__global__ __launch_bounds__(256) void k_final(const float* __restrict__ x,
                                               const float* __restrict__ Bo,
                                               float* __restrict__ out) {
    int t = blockIdx.x;
    float g0 = g_gp[t], g1 = g_gp[Tn + t];
    int e0 = g_e[t], e1 = g_e[Tn + t];
    __shared__ float su0[16], su1[16];
    if (threadIdx.x < 16) {
        su0[threadIdx.x] = g_u2[t * 16 + threadIdx.x];
        su1[threadIdx.x] = g_u2[(Tn + t) * 16 + threadIdx.x];
    }
    __syncthreads();
    float gs = g0 + g1;
    const float* B0 = Bo + (size_t)e0 * 16 * Dd;
    const float* B1 = Bo + (size_t)e1 * 16 * Dd;
    for (int d = threadIdx.x; d < Dd; d += 256) {
        float w = g_w[(size_t)t * Dd + d];
        float acc = x[(size_t)t * Dd + d] + w + gs * w;
        if (g0 != 0.f) {
            float dsum = 0.f;
            #pragma unroll
            for (int r = 0; r < 16; r++) dsum += su0[r] * B0[r * Dd + d];
            acc += 2.f * g0 * dsum;
        }
        if (g1 != 0.f) {
            float dsum = 0.f;
            #pragma unroll
            for (int r = 0; r < 16; r++) dsum += su1[r] * B1[r * Dd + d];
            acc += 2.f * g1 * dsum;
        }
        out[(size_t)t * Dd + d] = acc;
    }
}

// ---------------- launch ----------------
extern "C" void kernel_launch(void* const* d_in, const int* in_sizes, int n_in,
                              void* d_out, int out_size) {
    const float* x   = (const float*)d_in[0];
    const float* rp  = (const float*)d_in[1];
    const float* lnw = (const float*)d_in[2];
    const float* Wg  = (const float*)d_in[3];
    const float* Wi  = (const float*)d_in[4];
    const float* Wo  = (const float*)d_in[5];
    const float* Ai  = (const float*)d_in[6];
    const float* Bi  = (const float*)d_in[7];
    const float* Ao  = (const float*)d_in[8];
    const float* Bo  = (const float*)d_in[9];
    float* out = (float*)d_out;

    k_init<<<1, 128>>>();
    k_rms<<<Tn, 256>>>(x, lnw);
    k_logits<<<Tn / 16, 256>>>(Wg, out);
    k_gate<<<Tn / 256, 256>>>(rp, out);
    k_scan<<<Bbat, 32>>>(out);
    k_aux<<<1, 128>>>(out);

    dim3 gu(Tn, 2);
    k_u1<<<gu, 128>>>(Ai);

    k_gemm1<<<dim3(Ff / 128, Tn / 128), 256>>>(Wi);
    k_h<<<Tn, 256>>>(Bi);
    k_gemm2<<<dim3(Dd / 128, Tn / 128), 256>>>(Wo);
    k_u2<<<gu, 128>>>(Ao);
    k_final<<<Tn, 256>>>(x, Bo, out);
}

// round 4
// speedup vs baseline: 1.7886x; 1.7886x over previous
#include <cuda_runtime.h>
#include <cuda_bf16.h>
#include <math.h>
#include <stdint.h>

// Problem constants
#define Tn 16384            // B*N tokens
#define Dd 768
#define Ff 3072
#define Ee 16
#define CAPc 160
#define Bbat 8
#define Nseq 2048

#define K3_1 2304           // 3*Dd  (split-bf16 K for GEMM1)
#define K3_2 9216           // 3*Ff  (split-bf16 K for GEMM2)

// Output layout (float32, concatenated in reference return order)
#define OFF_AUX    12582912
#define OFF_BAL    12582913
#define OFF_ZL     12582914
#define OFF_LOGITS 12582915ll
#define OFF_ENERGY 12845059ll
#define OFF_GIDX   12861443ll

// ---------------- scratch (device globals; no runtime allocation) ----------------
__device__ float g_wi[(size_t)Tn * Dd];     // RMS-normed input (fp32)
__device__ float g_h [(size_t)Tn * Ff];     // z, then h in-place (fp32)
__device__ float g_w [(size_t)Tn * Dd];     // h @ Wo^T
__device__ __nv_bfloat16 g_A1[(size_t)Tn * K3_1];   // [wi_hi | wi_lo | wi_hi]
__device__ __nv_bfloat16 g_B1[(size_t)Ff * K3_1];   // [Wi_hi | Wi_hi | Wi_lo]
__device__ __nv_bfloat16 g_A2[(size_t)Tn * K3_2];   // [h_hi | h_lo | h_hi]
__device__ __nv_bfloat16 g_B2[(size_t)Dd * K3_2];   // [Wo_hi | Wo_hi | Wo_lo]
__device__ float g_u1[2 * Tn * 16];
__device__ float g_u2[2 * Tn * 16];
__device__ int   g_e  [2 * Tn];
__device__ float g_gate[2 * Tn];
__device__ float g_gp  [2 * Tn];
__device__ int   g_sh1 [Tn];
__device__ float g_dp[Bbat * Ee];
__device__ float g_d1[Bbat * Ee];
__device__ float g_zl;

// ---------------- PTX helpers (sm_100-safe: cp.async + ldmatrix + mma.sync) ----------------
__device__ __forceinline__ uint32_t s2u(const void* p) {
    uint32_t a;
    asm("{ .reg .u64 t; cvta.to.shared.u64 t, %1; cvt.u32.u64 %0, t; }" : "=r"(a) : "l"(p));
    return a;
}
__device__ __forceinline__ void cpa16(uint32_t s, const void* g) {
    asm volatile("cp.async.cg.shared.global [%0], [%1], 16;\n" :: "r"(s), "l"(g));
}
#define CPA_COMMIT() asm volatile("cp.async.commit_group;\n" ::: "memory")
#define CPA_WAIT1()  asm volatile("cp.async.wait_group 1;\n" ::: "memory")

__device__ __forceinline__ void ldsm4(uint32_t* r, uint32_t a) {
    asm volatile("ldmatrix.sync.aligned.m8n8.x4.shared.b16 {%0,%1,%2,%3}, [%4];"
                 : "=r"(r[0]), "=r"(r[1]), "=r"(r[2]), "=r"(r[3]) : "r"(a));
}
__device__ __forceinline__ void mma16816(float* c, const uint32_t* a, uint32_t b0, uint32_t b1) {
    asm volatile("mma.sync.aligned.m16n8k16.row.col.f32.bf16.bf16.f32 "
                 "{%0,%1,%2,%3}, {%4,%5,%6,%7}, {%8,%9}, {%0,%1,%2,%3};"
                 : "+f"(c[0]), "+f"(c[1]), "+f"(c[2]), "+f"(c[3])
                 : "r"(a[0]), "r"(a[1]), "r"(a[2]), "r"(a[3]), "r"(b0), "r"(b1));
}

#define SWZ(o) ((o) ^ (((o) >> 3) & 0x70))

// GEMM smem: A stages [128][64]bf16 = 16KB, B stages [256][64]bf16 = 32KB, 3 stages
#define SM_A(s) ((s) * 16384)
#define SM_B(s) (49152 + (s) * 32768)
#define SMEM_GEMM 147456

// ---------------- mma.sync split-bf16 GEMM: C[m,n] = sum_k A[m,k]*B[n,k] ----------------
// Tile 128(M) x 256(N), K-chunk 64, 3-stage cp.async pipeline, 512 threads (16 warps 4Mx4N).
__global__ __launch_bounds__(512, 1)
void k_tc_gemm(const __nv_bfloat16* __restrict__ A, const __nv_bfloat16* __restrict__ B,
               float* __restrict__ C, int Ncols, int K3, int KI) {
    extern __shared__ char smem[];
    const uint32_t sb = s2u(smem);
    const int tid = threadIdx.x;
    const int wid = tid >> 5;
    const int lane = tid & 31;
    const int warp_m = wid & 3;          // 4 groups of M=32
    const int warp_n = wid >> 2;         // 4 groups of N=64
    const int bm = blockIdx.y * 128;
    const int bn = blockIdx.x * 256;

    float acc[2][8][4];
    #pragma unroll
    for (int i = 0; i < 2; i++)
        #pragma unroll
        for (int j = 0; j < 8; j++)
            #pragma unroll
            for (int q = 0; q < 4; q++) acc[i][j][q] = 0.f;

    // prologue: stages 0,1
    #pragma unroll
    for (int c = 0; c < 2; c++) {
        const int kc = c * 64;
        #pragma unroll
        for (int j = 0; j < 2; j++) {
            int idx = tid + 512 * j, row = idx >> 3, seg = idx & 7;
            cpa16(sb + SM_A(c) + SWZ(row * 128 + seg * 16),
                  A + (size_t)(bm + row) * K3 + kc + seg * 8);
        }
        #pragma unroll
        for (int j = 0; j < 4; j++) {
            int idx = tid + 512 * j, row = idx >> 3, seg = idx & 7;
            cpa16(sb + SM_B(c) + SWZ(row * 128 + seg * 16),
                  B + (size_t)(bn + row) * K3 + kc + seg * 8);
        }
        CPA_COMMIT();
    }

    for (int i = 0; i < KI; i++) {
        const int si = i % 3;
        CPA_WAIT1();
        __syncthreads();

        // prefetch chunk i+2 into the slot freed at iter i-1
        const int j = i + 2;
        if (j < KI) {
            const int sj = j % 3;
            const int kc = j * 64;
            #pragma unroll
            for (int jj = 0; jj < 2; jj++) {
                int idx = tid + 512 * jj, row = idx >> 3, seg = idx & 7;
                cpa16(sb + SM_A(sj) + SWZ(row * 128 + seg * 16),
                      A + (size_t)(bm + row) * K3 + kc + seg * 8);
            }
            #pragma unroll
            for (int jj = 0; jj < 4; jj++) {
                int idx = tid + 512 * jj, row = idx >> 3, seg = idx & 7;
                cpa16(sb + SM_B(sj) + SWZ(row * 128 + seg * 16),
                      B + (size_t)(bn + row) * K3 + kc + seg * 8);
            }
        }
        CPA_COMMIT();

        // compute chunk i: 4 k-steps of 16
        const uint32_t sa = sb + SM_A(si);
        const uint32_t sB = sb + SM_B(si);
        #pragma unroll
        for (int ks = 0; ks < 4; ks++) {
            uint32_t a[2][4];
            #pragma unroll
            for (int mt = 0; mt < 2; mt++) {
                int row = warp_m * 32 + mt * 16 + (lane & 15);
                ldsm4(a[mt], sa + SWZ(row * 128 + ks * 32 + ((lane >> 4) << 4)));
            }
            // B fragments: non-trans ldmatrix; B smem is [n][k] (K contiguous).
            // lane L: matrix m = L>>3 (m0:n0-7/k0-7, m1:n0-7/k8-15, m2:n8-15/k0-7, m3:n8-15/k8-15)
            uint32_t b[4][4];
            #pragma unroll
            for (int g = 0; g < 4; g++) {
                int nr = warp_n * 64 + g * 16 + ((lane >> 4) << 3) + (lane & 7);
                ldsm4(b[g], sB + SWZ(nr * 128 + ks * 32 + (((lane >> 3) & 1) << 4)));
            }
            #pragma unroll
            for (int mt = 0; mt < 2; mt++)
                #pragma unroll
                for (int nt = 0; nt < 8; nt++) {
                    int g = nt >> 1, hf = (nt & 1) << 1;
                    mma16816(acc[mt][nt], a[mt], b[g][hf], b[g][hf + 1]);
                }
        }
        __syncthreads();
    }

    // epilogue: direct fp32 stores (each quad covers 8 contiguous cols = 32B)
    #pragma unroll
    for (int mt = 0; mt < 2; mt++) {
        int r0 = bm + warp_m * 32 + mt * 16 + (lane >> 2);
        #pragma unroll
        for (int nt = 0; nt < 8; nt++) {
            int col = bn + warp_n * 64 + nt * 8 + (lane & 3) * 2;
            *(float2*)(C + (size_t)r0 * Ncols + col)       = make_float2(acc[mt][nt][0], acc[mt][nt][1]);
            *(float2*)(C + (size_t)(r0 + 8) * Ncols + col) = make_float2(acc[mt][nt][2], acc[mt][nt][3]);
        }
    }
}

// ---------------- init ----------------
__global__ void k_init() {
    int i = threadIdx.x;
    if (i < Bbat * Ee) g_dp[i] = 0.f;
    if (i == 0) g_zl = 0.f;
}

// ---------------- RMS norm (+ split-bf16 A1 build) ----------------
__global__ __launch_bounds__(256) void k_rms(const float* __restrict__ x,
                                             const float* __restrict__ lnw) {
    int t = blockIdx.x;
    const float* xr = x + (size_t)t * Dd;
    float s = 0.f;
    for (int d = threadIdx.x; d < Dd; d += 256) { float v = xr[d]; s += v * v; }
    __shared__ float red[256];
    red[threadIdx.x] = s; __syncthreads();
    for (int o = 128; o > 0; o >>= 1) {
        if (threadIdx.x < o) red[threadIdx.x] += red[threadIdx.x + o];
        __syncthreads();
    }
    float inv = rsqrtf(red[0] / (float)Dd + 1e-6f);
    __nv_bfloat16* a1 = g_A1 + (size_t)t * K3_1;
    for (int d = threadIdx.x; d < Dd; d += 256) {
        float v = xr[d] * inv * lnw[d];
        g_wi[(size_t)t * Dd + d] = v;
        __nv_bfloat16 hi = __float2bfloat16(v);
        __nv_bfloat16 lo = __float2bfloat16(v - __bfloat162float(hi));
        a1[d] = hi; a1[Dd + d] = lo; a1[2 * Dd + d] = hi;
    }
}

// ---------------- weight splits ----------------
__global__ __launch_bounds__(256) void k_splitB1(const float* __restrict__ Wi) {
    int r = blockIdx.x;
    __nv_bfloat16* b1 = g_B1 + (size_t)r * K3_1;
    const float* wr = Wi + (size_t)r * Dd;
    for (int d = threadIdx.x; d < Dd; d += 256) {
        float v = wr[d];
        __nv_bfloat16 hi = __float2bfloat16(v);
        __nv_bfloat16 lo = __float2bfloat16(v - __bfloat162float(hi));
        b1[d] = hi; b1[Dd + d] = hi; b1[2 * Dd + d] = lo;
    }
}
__global__ __launch_bounds__(256) void k_splitB2(const float* __restrict__ Wo) {
    int r = blockIdx.x;
    __nv_bfloat16* b2 = g_B2 + (size_t)r * K3_2;
    const float* wr = Wo + (size_t)r * Ff;
    for (int d = threadIdx.x; d < Ff; d += 256) {
        float v = wr[d];
        __nv_bfloat16 hi = __float2bfloat16(v);
        __nv_bfloat16 lo = __float2bfloat16(v - __bfloat162float(hi));
        b2[d] = hi; b2[Ff + d] = hi; b2[2 * Ff + d] = lo;
    }
}

// ---------------- logits = wi_in @ Wg^T ----------------
__global__ __launch_bounds__(256) void k_logits(const float* __restrict__ Wg,
                                                float* __restrict__ out) {
    __shared__ float sWg[Dd * 16];
    for (int i = threadIdx.x; i < Dd * 16; i += 256) {
        int e = i / Dd, d = i % Dd;
        sWg[d * 16 + e] = Wg[i];
    }
    __syncthreads();
    int tok = blockIdx.x * 16 + (threadIdx.x >> 4);
    int e = threadIdx.x & 15;
    const float* wr = g_wi + (size_t)tok * Dd;
    float s = 0.f;
    #pragma unroll 4
    for (int d = 0; d < Dd; d++) s += wr[d] * sWg[d * 16 + e];
    out[OFF_LOGITS + (size_t)tok * 16 + e] = s;
}

// ---------------- softmax / top2 / gates / aux partials ----------------
__global__ __launch_bounds__(256) void k_gate(const float* __restrict__ rp,
                                              float* __restrict__ out) {
    int t = blockIdx.x * 256 + threadIdx.x;
    const float* lg = out + OFF_LOGITS + (size_t)t * 16;
    float l[16];
    float mx = -1e30f;
    #pragma unroll
    for (int e = 0; e < 16; e++) { l[e] = lg[e]; mx = fmaxf(mx, l[e]); }
    float se = 0.f;
    #pragma unroll
    for (int e = 0; e < 16; e++) se += expf(l[e] - mx);
    float lse = mx + logf(se);
    out[OFF_ENERGY + t] = -lse;

    int e0 = 0; float b0 = l[0];
    #pragma unroll
    for (int e = 1; e < 16; e++) if (l[e] > b0) { b0 = l[e]; e0 = e; }
    int e1 = -1; float b1 = -1e30f;
    #pragma unroll
    for (int e = 0; e < 16; e++) if (e != e0 && l[e] > b1) { b1 = l[e]; e1 = e; }
    float v0 = expf(b0 - lse), v1 = expf(b1 - lse);
    float den = v0 + v1; if (den < 1e-9f) den = 1e-9f;
    float G0 = v0 / den, G1 = v1 / den;
    g_e[t] = e0; g_e[Tn + t] = e1;
    g_gate[t] = G0; g_gate[Tn + t] = G1;
    g_sh1[t] = (rp[Tn + t] < G1 * 5.0f) ? 1 : 0;

    __shared__ float sdp[16];
    __shared__ float szl;
    if (threadIdx.x < 16) sdp[threadIdx.x] = 0.f;
    if (threadIdx.x == 0) szl = 0.f;
    __syncthreads();
    #pragma unroll
    for (int e = 0; e < 16; e++) atomicAdd(&sdp[e], expf(l[e] - lse));
    atomicAdd(&szl, lse * lse);
    __syncthreads();
    int b = t >> 11;
    if (threadIdx.x < 16) atomicAdd(&g_dp[b * 16 + threadIdx.x], sdp[threadIdx.x]);
    if (threadIdx.x == 0) atomicAdd(&g_zl, szl);
}

// ---------------- capacity scan ----------------
__global__ void k_scan(float* __restrict__ out) {
    if (threadIdx.x != 0) return;
    int b = blockIdx.x;
    int base = b * Nseq;
    int c0[16];
    #pragma unroll
    for (int e = 0; e < 16; e++) c0[e] = 0;
    for (int n = 0; n < Nseq; n++) {
        int t = base + n;
        int e = g_e[t];
        int pos = c0[e]++;
        bool s = pos < CAPc;
        g_gp[t] = s ? g_gate[t] : 0.f;
        out[OFF_GIDX + t] = s ? (float)e : 0.f;
    }
    int c1[16];
    #pragma unroll
    for (int e = 0; e < 16; e++) {
        int sv = c0[e] < CAPc ? c0[e] : CAPc;
        g_d1[b * 16 + e] = (float)sv / (float)Nseq;
        c1[e] = sv;
    }
    for (int n = 0; n < Nseq; n++) {
        int t = base + n;
        if (g_sh1[t]) {
            int e = g_e[Tn + t];
            int pos = c1[e]++;
            bool s = pos < CAPc;
            g_gp[Tn + t] = s ? g_gate[Tn + t] : 0.f;
            out[OFF_GIDX + Tn + t] = s ? (float)e : 0.f;
        } else {
            g_gp[Tn + t] = 0.f;
            out[OFF_GIDX + Tn + t] = 0.f;
        }
    }
}

// ---------------- aux scalars ----------------
__global__ void k_aux(float* __restrict__ out) {
    __shared__ float red[128];
    int i = threadIdx.x;
    red[i] = (g_dp[i] / (float)Nseq) * g_d1[i];
    __syncthreads();
    for (int o = 64; o > 0; o >>= 1) {
        if (i < o) red[i] += red[i + o];
        __syncthreads();
    }
    if (i == 0) {
        float bal = red[0] * 2.0f;
        float zl = g_zl / (float)Tn;
        out[OFF_BAL] = bal;
        out[OFF_ZL] = zl;
        out[OFF_AUX] = 0.01f * bal + 0.01f * zl;
    }
}

// ---------------- LoRA u vectors ----------------
__global__ __launch_bounds__(128) void k_u1(const float* __restrict__ Ai) {
    int t = blockIdx.x, k = blockIdx.y;
    int idx = k * Tn + t;
    float gp = g_gp[idx];
    if (gp == 0.f) {
        if (threadIdx.x < 16) g_u1[idx * 16 + threadIdx.x] = 0.f;
        return;
    }
    int e = g_e[idx];
    int r = threadIdx.x & 15, seg = threadIdx.x >> 4;
    const float* Ae = Ai + (size_t)e * Dd * 16;
    const float* wr = g_wi + (size_t)t * Dd;
    float acc = 0.f;
    int d0 = seg * 96;
    #pragma unroll 4
    for (int d = d0; d < d0 + 96; d++) acc += wr[d] * Ae[d * 16 + r];
    __shared__ float red[128];
    red[threadIdx.x] = acc; __syncthreads();
    if (threadIdx.x < 16) {
        float s = 0.f;
        #pragma unroll
        for (int j = 0; j < 8; j++) s += red[j * 16 + r];
        g_u1[idx * 16 + r] = s;
    }
}

__global__ __launch_bounds__(128) void k_u2(const float* __restrict__ Ao) {
    int t = blockIdx.x, k = blockIdx.y;
    int idx = k * Tn + t;
    float gp = g_gp[idx];
    if (gp == 0.f) {
        if (threadIdx.x < 16) g_u2[idx * 16 + threadIdx.x] = 0.f;
        return;
    }
    int e = g_e[idx];
    int r = threadIdx.x & 15, seg = threadIdx.x >> 4;
    const float* Ae = Ao + (size_t)e * Ff * 16;
    const float* hr = g_h + (size_t)t * Ff;
    float acc = 0.f;
    int d0 = seg * 384;
    #pragma unroll 4
    for (int d = d0; d < d0 + 384; d++) acc += hr[d] * Ae[d * 16 + r];
    __shared__ float red[128];
    red[threadIdx.x] = acc; __syncthreads();
    if (threadIdx.x < 16) {
        float s = 0.f;
        #pragma unroll
        for (int j = 0; j < 8; j++) s += red[j * 16 + r];
        g_u2[idx * 16 + r] = s;
    }
}

// ---------------- h = relu(z) + sum_k g'_k (z + 2*u_k@Bi[e_k]), + A2 build ----------------
__global__ __launch_bounds__(256) void k_h(const float* __restrict__ Bi) {
    int t = blockIdx.x;
    float g0 = g_gp[t], g1 = g_gp[Tn + t];
    int e0 = g_e[t], e1 = g_e[Tn + t];
    __shared__ float su0[16], su1[16];
    if (threadIdx.x < 16) {
        su0[threadIdx.x] = g_u1[t * 16 + threadIdx.x];
        su1[threadIdx.x] = g_u1[(Tn + t) * 16 + threadIdx.x];
    }
    __syncthreads();
    float gs = g0 + g1;
    const float* B0 = Bi + (size_t)e0 * 16 * Ff;
    const float* B1 = Bi + (size_t)e1 * 16 * Ff;
    float* hr = g_h + (size_t)t * Ff;
    __nv_bfloat16* a2 = g_A2 + (size_t)t * K3_2;
    for (int f = threadIdx.x; f < Ff; f += 256) {
        float z = hr[f];
        float acc = fmaxf(z, 0.f) + gs * z;
        if (g0 != 0.f) {
            float dsum = 0.f;
            #pragma unroll
            for (int r = 0; r < 16; r++) dsum += su0[r] * B0[r * Ff + f];
            acc += 2.f * g0 * dsum;
        }
        if (g1 != 0.f) {
            float dsum = 0.f;
            #pragma unroll
            for (int r = 0; r < 16; r++) dsum += su1[r] * B1[r * Ff + f];
            acc += 2.f * g1 * dsum;
        }
        hr[f] = acc;
        __nv_bfloat16 hi = __float2bfloat16(acc);
        __nv_bfloat16 lo = __float2bfloat16(acc - __bfloat162float(hi));
        a2[f] = hi; a2[Ff + f] = lo; a2[2 * Ff + f] = hi;
    }
}

// ---------------- out = x + w + sum_k g'_k (w + 2*u2_k@Bo[e_k]) ----------------
__global__ __launch_bounds__(256) void k_final(const float* __restrict__ x,
                                               const float* __restrict__ Bo,
                                               float* __restrict__ out) {
    int t = blockIdx.x;
    float g0 = g_gp[t], g1 = g_gp[Tn + t];
    int e0 = g_e[t], e1 = g_e[Tn + t];
    __shared__ float su0[16], su1[16];
    if (threadIdx.x < 16) {
        su0[threadIdx.x] = g_u2[t * 16 + threadIdx.x];
        su1[threadIdx.x] = g_u2[(Tn + t) * 16 + threadIdx.x];
    }
    __syncthreads();
    float gs = g0 + g1;
    const float* B0 = Bo + (size_t)e0 * 16 * Dd;
    const float* B1 = Bo + (size_t)e1 * 16 * Dd;
    for (int d = threadIdx.x; d < Dd; d += 256) {
        float w = g_w[(size_t)t * Dd + d];
        float acc = x[(size_t)t * Dd + d] + w + gs * w;
        if (g0 != 0.f) {
            float dsum = 0.f;
            #pragma unroll
            for (int r = 0; r < 16; r++) dsum += su0[r] * B0[r * Dd + d];
            acc += 2.f * g0 * dsum;
        }
        if (g1 != 0.f) {
            float dsum = 0.f;
            #pragma unroll
            for (int r = 0; r < 16; r++) dsum += su1[r] * B1[r * Dd + d];
            acc += 2.f * g1 * dsum;
        }
        out[(size_t)t * Dd + d] = acc;
    }
}

// ---------------- launch ----------------
extern "C" void kernel_launch(void* const* d_in, const int* in_sizes, int n_in,
                              void* d_out, int out_size) {
    const float* x   = (const float*)d_in[0];
    const float* rp  = (const float*)d_in[1];
    const float* lnw = (const float*)d_in[2];
    const float* Wg  = (const float*)d_in[3];
    const float* Wi  = (const float*)d_in[4];
    const float* Wo  = (const float*)d_in[5];
    const float* Ai  = (const float*)d_in[6];
    const float* Bi  = (const float*)d_in[7];
    const float* Ao  = (const float*)d_in[8];
    const float* Bo  = (const float*)d_in[9];
    float* out = (float*)d_out;

    cudaFuncSetAttribute(k_tc_gemm, cudaFuncAttributeMaxDynamicSharedMemorySize, SMEM_GEMM);

    __nv_bfloat16 *A1p, *B1p, *A2p, *B2p;
    float *hp, *wp;
    cudaGetSymbolAddress((void**)&A1p, g_A1);
    cudaGetSymbolAddress((void**)&B1p, g_B1);
    cudaGetSymbolAddress((void**)&A2p, g_A2);
    cudaGetSymbolAddress((void**)&B2p, g_B2);
    cudaGetSymbolAddress((void**)&hp, g_h);
    cudaGetSymbolAddress((void**)&wp, g_w);

    k_init<<<1, 128>>>();
    k_rms<<<Tn, 256>>>(x, lnw);
    k_splitB1<<<Ff, 256>>>(Wi);
    k_splitB2<<<Dd, 256>>>(Wo);
    k_logits<<<Tn / 16, 256>>>(Wg, out);
    k_gate<<<Tn / 256, 256>>>(rp, out);
    k_scan<<<Bbat, 32>>>(out);
    k_aux<<<1, 128>>>(out);

    dim3 gu(Tn, 2);
    k_u1<<<gu, 128>>>(Ai);

    // GEMM1: z = wi_in @ Wi^T   [16384 x 3072], K3 = 2304
    k_tc_gemm<<<dim3(Ff / 256, Tn / 128), 512, SMEM_GEMM>>>(A1p, B1p, hp, Ff, K3_1, K3_1 / 64);
    k_h<<<Tn, 256>>>(Bi);
    // GEMM2: w = h @ Wo^T       [16384 x 768], K3 = 9216
    k_tc_gemm<<<dim3(Dd / 256, Tn / 128), 512, SMEM_GEMM>>>(A2p, B2p, wp, Dd, K3_2, K3_2 / 64);
    k_u2<<<gu, 128>>>(Ao);
    k_final<<<Tn, 256>>>(x, Bo, out);
}